// round 8
// baseline (speedup 1.0000x reference)
#include <cuda_runtime.h>
#include <cuda_bf16.h>
#include <mma.h>
#include <cstdint>
#include <type_traits>
#include <math.h>
using namespace nvcuda;

#define BATCH 4
#define SEQL  1024
#define DMODEL 512
#define NHEAD 8
#define DK 64
#define NLAYERS 3
#define DFF 2048
#define INPUT_DIM 128
#define NUM_CLASSES 64
#define ROWS 4096
#define TOPU 34
#define BH 32
#define BK 32
#define NSTG 3
#define PSLOTS 128
// fused scores+topk tile params
#define QROWS 16
#define KCH 64
#define LSC 1032
#define LKB 80
typedef __nv_bfloat16 bf16;

// ---------------- scratch (static device globals) ----------------
__device__ __align__(16) float g_h [DMODEL*ROWS];     // h_t  [feature][token] fp32
__device__ __align__(16) float g_t2[DMODEL*ROWS];     // tmp2_t fp32
__device__ __align__(16) float g_bcat[NLAYERS*2*DMODEL];
__device__ __align__(16) bf16 g_x0[INPUT_DIM*ROWS], g_x1[INPUT_DIM*ROWS];     // x_t planes
__device__ __align__(16) bf16 g_h0[DMODEL*ROWS],  g_h1[DMODEL*ROWS];          // h_t planes
__device__ __align__(16) bf16 g_qk0[2*DMODEL*ROWS], g_qk1[2*DMODEL*ROWS];     // Q_t then K_t
__device__ __align__(16) bf16 g_v0[ROWS*DMODEL],  g_v1[ROWS*DMODEL];          // V token-major
__device__ __align__(16) bf16 g_a0[ROWS*DMODEL],  g_a1[ROWS*DMODEL];          // attn token-major
__device__ __align__(16) bf16 g_f0[DFF*ROWS],     g_f1[DFF*ROWS];             // ff_t planes
// compact sparse P
__device__ __align__(16) int   g_pidx[(long long)BH*SEQL*PSLOTS];
__device__ __align__(16) float g_pval[(long long)BH*SEQL*PSLOTS];
__device__ __align__(16) int   g_pcnt[BH*SEQL];

// weight arena
#define W_EMB 0
#define W_Qo(l) (65536LL   + (long long)(l)*262144)
#define W_Ko(l) (851968LL  + (long long)(l)*262144)
#define W_Vo(l) (1638400LL + (long long)(l)*262144)
#define W_Oo(l) (2424832LL + (long long)(l)*262144)
#define W_1o(l) (3211264LL + (long long)(l)*1048576)
#define W_2o(l) (6356992LL + (long long)(l)*1048576)
#define W_DEC 9502720LL
#define WT_TOTAL 9535488LL
__device__ __align__(16) bf16 g_w0[WT_TOTAL], g_w1[WT_TOTAL];

// ---------------- helpers ----------------
__device__ __forceinline__ uint32_t smem_to_u32(const void* p) {
    uint32_t a;
    asm("{ .reg .u64 t; cvta.to.shared.u64 t, %1; cvt.u32.u64 %0, t; }" : "=r"(a) : "l"(p));
    return a;
}
__device__ __forceinline__ void cp16(uint32_t s, const bf16* g) {
    asm volatile("{ .reg .u64 p; cvta.to.global.u64 p, %1; cp.async.cg.shared.global [%0], [p], 16; }"
                 :: "r"(s), "l"(g) : "memory");
}
__device__ __forceinline__ void cp_commit() { asm volatile("cp.async.commit_group;" ::: "memory"); }
__device__ __forceinline__ void cp_wait2()  { asm volatile("cp.async.wait_group 2;" ::: "memory"); }
__device__ __forceinline__ void cp_wait1()  { asm volatile("cp.async.wait_group 1;" ::: "memory"); }
__device__ __forceinline__ void cp_wait0()  { asm volatile("cp.async.wait_group 0;" ::: "memory"); }

__device__ __forceinline__ void split2(float v, bf16& s0, bf16& s1) {
    s0 = __float2bfloat16_rn(v);
    s1 = __float2bfloat16_rn(v - __bfloat162float(s0));
}

// ---------------- bf16x2 tensor GEMM (3-stage cp.async pipeline) ----------------
template<int MT, int NT, int BIAS, int EPI, bool BCOL, bool RELU>
__global__ __launch_bounds__(256, 2)
void gk(const bf16* __restrict__ A0, const bf16* __restrict__ A1,
        int lda, long long sAo, long long sAi,
        const bf16* __restrict__ B0, const bf16* __restrict__ B1,
        int ldb, long long sBo, long long sBi,
        float* __restrict__ C, bf16* __restrict__ C0, bf16* __restrict__ C1,
        int ldc, long long sCo, long long sCi,
        int K, const float* __restrict__ bias, long long sBias, float alpha)
{
    extern __shared__ char smc[];
    constexpr int LA = MT + 8;
    constexpr int SZA = BK * LA;
    constexpr int LB = BCOL ? (BK + 8) : (NT + 8);
    constexpr int SZB = BCOL ? (NT * LB) : (BK * LB);
    constexpr int A_ELEMS = NSTG * 2 * SZA;
    constexpr int LS = NT + 4;
    bf16* As = (bf16*)smc;
    bf16* Bs = As + A_ELEMS;
    float* stg = (float*)smc;

    const uint32_t smb = smem_to_u32(smc);
    const uint32_t smB = smb + A_ELEMS * 2;
    const int tid = threadIdx.x, wid = tid >> 5;
    const int z = blockIdx.z;
    const int bm = blockIdx.y * MT, bn = blockIdx.x * NT;
    const long long zA = (long long)(z >> 3) * sAo + (long long)(z & 7) * sAi;
    const long long zB = (long long)(z >> 3) * sBo + (long long)(z & 7) * sBi;
    const long long zC = (long long)(z >> 3) * sCo + (long long)(z & 7) * sCi;
    const bf16* Ap[2] = { A0 + zA, A1 + zA };
    const bf16* Bp[2] = { B0 + zB, B1 + zB };

    constexpr int WN_CNT = NT / 32;
    constexpr int WM = MT * WN_CNT / 8;
    constexpr int FM = WM / 16;
    const int wm = (wid / WN_CNT) * WM;
    const int wn = (wid % WN_CNT) * 32;

    using FragA = wmma::fragment<wmma::matrix_a, 16, 16, 16, bf16, wmma::col_major>;
    using BLay  = typename std::conditional<BCOL, wmma::col_major, wmma::row_major>::type;
    using FragB = wmma::fragment<wmma::matrix_b, 16, 16, 16, bf16, BLay>;
    wmma::fragment<wmma::accumulator, 16, 16, 16, float> acc[FM][2];
#pragma unroll
    for (int i = 0; i < FM; i++)
#pragma unroll
        for (int j = 0; j < 2; j++) wmma::fill_fragment(acc[i][j], 0.f);

    auto load_stage = [&](int c, int st) {
        const int k0 = c * BK;
#pragma unroll
        for (int p = 0; p < 2; p++) {
            const bf16* ap = Ap[p];
            for (int t = tid; t < 4 * MT; t += 256) {
                int k = t / (MT / 8), ch = t % (MT / 8);
                uint32_t d = smb + (uint32_t)(((st * 2 + p) * SZA + k * LA + ch * 8) * 2);
                cp16(d, ap + (long long)(k0 + k) * lda + bm + ch * 8);
            }
            const bf16* bp = Bp[p];
            if (!BCOL) {
                for (int t = tid; t < 4 * NT; t += 256) {
                    int k = t / (NT / 8), ch = t % (NT / 8);
                    uint32_t d = smB + (uint32_t)(((st * 2 + p) * SZB + k * LB + ch * 8) * 2);
                    cp16(d, bp + (long long)(k0 + k) * ldb + bn + ch * 8);
                }
            } else {
                for (int t = tid; t < 4 * NT; t += 256) {
                    int n = t >> 2, ch = t & 3;
                    uint32_t d = smB + (uint32_t)(((st * 2 + p) * SZB + n * LB + ch * 8) * 2);
                    cp16(d, bp + (long long)(bn + n) * ldb + k0 + ch * 8);
                }
            }
        }
        cp_commit();
    };

    const int nch = K / BK;
    load_stage(0, 0);
    load_stage(1, 1);

    for (int c = 0; c < nch; c++) {
        const int st = c % NSTG;
        if (c + 2 < nch) { load_stage(c + 2, (c + 2) % NSTG); cp_wait2(); }
        else if (c + 1 < nch) cp_wait1();
        else cp_wait0();
        __syncthreads();
#pragma unroll
        for (int ks = 0; ks < 2; ks++) {
            FragB bfr[2][2];
#pragma unroll
            for (int p = 0; p < 2; p++)
#pragma unroll
                for (int j = 0; j < 2; j++) {
                    const bf16* ptr = Bs + (st * 2 + p) * SZB +
                        (BCOL ? ((wn + j * 16) * LB + ks * 16) : (ks * 16 * LB + wn + j * 16));
                    wmma::load_matrix_sync(bfr[p][j], ptr, LB);
                }
#pragma unroll
            for (int i = 0; i < FM; i++) {
                FragA a0, a1;
                wmma::load_matrix_sync(a0, As + (st * 2 + 0) * SZA + ks * 16 * LA + wm + i * 16, LA);
                wmma::load_matrix_sync(a1, As + (st * 2 + 1) * SZA + ks * 16 * LA + wm + i * 16, LA);
#pragma unroll
                for (int j = 0; j < 2; j++) {
                    wmma::mma_sync(acc[i][j], a0, bfr[0][j], acc[i][j]);
                    wmma::mma_sync(acc[i][j], a0, bfr[1][j], acc[i][j]);
                    wmma::mma_sync(acc[i][j], a1, bfr[0][j], acc[i][j]);
                }
            }
        }
        __syncthreads();
    }

#pragma unroll
    for (int i = 0; i < FM; i++)
#pragma unroll
        for (int j = 0; j < 2; j++)
            wmma::store_matrix_sync(&stg[(wm + i * 16) * LS + wn + j * 16], acc[i][j], LS, wmma::mem_row_major);
    __syncthreads();

    for (int t = tid; t < MT * NT / 4; t += 256) {
        int row = t / (NT / 4), c4 = (t % (NT / 4)) * 4;
        float4 v = *(float4*)&stg[row * LS + c4];
        v.x *= alpha; v.y *= alpha; v.z *= alpha; v.w *= alpha;
        if (BIAS == 1) {
            float bb = bias[(z & 7) * sBias + bm + row];
            v.x += bb; v.y += bb; v.z += bb; v.w += bb;
        } else if (BIAS == 2) {
            const float* bp = bias + (z & 7) * sBias + bn + c4;
            v.x += bp[0]; v.y += bp[1]; v.z += bp[2]; v.w += bp[3];
        }
        if (RELU) {
            v.x = fmaxf(v.x, 0.f); v.y = fmaxf(v.y, 0.f);
            v.z = fmaxf(v.z, 0.f); v.w = fmaxf(v.w, 0.f);
        }
        long long idx = zC + (long long)(bm + row) * ldc + bn + c4;
        if (EPI == 0) {
            *(float4*)&C[idx] = v;
        } else {
            union { uint2 u; bf16 h[4]; } p0, p1;
            split2(v.x, p0.h[0], p1.h[0]);
            split2(v.y, p0.h[1], p1.h[1]);
            split2(v.z, p0.h[2], p1.h[2]);
            split2(v.w, p0.h[3], p1.h[3]);
            *(uint2*)&C0[idx] = p0.u;
            *(uint2*)&C1[idx] = p1.u;
        }
    }
}

// ---------------- fused scores + exact top-u + softmax -> compact sparse P ----------------
// CTA: 128 threads, QROWS=16 query rows of one (b,h). K streamed in KCH chunks.
// smem: Sc[QROWS][LSC] fp32 | Ks[2buf][2pl][64][LKB] | Qs[2pl][64][16] | hist[4][256]
__global__ __launch_bounds__(128, 2)
void sc_topk(const bf16* __restrict__ q0, const bf16* __restrict__ q1,
             const bf16* __restrict__ k0g, const bf16* __restrict__ k1g,
             int* __restrict__ pcnt, int* __restrict__ pidx, float* __restrict__ pval)
{
    extern __shared__ char smc[];
    float* Sc = (float*)smc;
    bf16* Ks = (bf16*)(smc + QROWS * LSC * 4);
    bf16* Qs = Ks + 2 * 2 * 64 * LKB;
    int* hist = (int*)(Qs + 2 * 64 * 16);

    const uint32_t smb = smem_to_u32(smc);
    const uint32_t smKs = smb + QROWS * LSC * 4;
    const uint32_t smQs = smKs + 2 * 2 * 64 * LKB * 2;

    const int tid = threadIdx.x, lane = tid & 31, w = tid >> 5;
    const int bh = blockIdx.y, b = bh >> 3, h = bh & 7;
    const long long qtok = (long long)b * SEQL + blockIdx.x * QROWS;
    const long long ktok = (long long)b * SEQL;
    const long long hoff = (long long)h * DK * ROWS;
    const bf16* Qp[2] = { q0 + hoff + qtok, q1 + hoff + qtok };
    const bf16* Kp[2] = { k0g + hoff + ktok, k1g + hoff + ktok };

    // Q tile: 2 planes x 64 d x 16 q  (256 cp16)
#pragma unroll
    for (int r = 0; r < 2; r++) {
        int t = tid * 2 + r;
        int p = t >> 7, d = (t >> 1) & 63, seg = t & 1;
        cp16(smQs + (uint32_t)((((p * 64 + d) * 16) + seg * 8) * 2),
             Qp[p] + (long long)d * ROWS + seg * 8);
    }
    auto loadK = [&](int c, int buf) {
#pragma unroll
        for (int r = 0; r < 8; r++) {
            int t = tid * 8 + r;                 // 0..1023
            int p = t >> 9, d = (t >> 3) & 63, seg = t & 7;
            cp16(smKs + (uint32_t)(((((buf * 2 + p) * 64 + d) * LKB) + seg * 8) * 2),
                 Kp[p] + (long long)d * ROWS + c * KCH + seg * 8);
        }
        cp_commit();
    };
    loadK(0, 0);   // group0 = Q + K0
    loadK(1, 1);   // group1 = K1

    using FragA = wmma::fragment<wmma::matrix_a, 16, 16, 16, bf16, wmma::col_major>;
    using FragB = wmma::fragment<wmma::matrix_b, 16, 16, 16, bf16, wmma::row_major>;
    FragA afr[2][4];
    bool aload = false;

    const int nchunk = SEQL / KCH;   // 16
    for (int c = 0; c < nchunk; c++) {
        if (c + 1 < nchunk) cp_wait1(); else cp_wait0();
        __syncthreads();
        if (!aload) {       // hoist A frags once Q is resident (group0 done)
#pragma unroll
            for (int p = 0; p < 2; p++)
#pragma unroll
                for (int ks = 0; ks < 4; ks++)
                    wmma::load_matrix_sync(afr[p][ks], Qs + (p * 64 + ks * 16) * 16, 16);
            aload = true;
        }
        const int buf = c & 1;
        wmma::fragment<wmma::accumulator, 16, 16, 16, float> acc;
        wmma::fill_fragment(acc, 0.f);
#pragma unroll
        for (int ks = 0; ks < 4; ks++) {
            FragB b0, b1;
            wmma::load_matrix_sync(b0, Ks + ((buf * 2 + 0) * 64 + ks * 16) * LKB + w * 16, LKB);
            wmma::load_matrix_sync(b1, Ks + ((buf * 2 + 1) * 64 + ks * 16) * LKB + w * 16, LKB);
            wmma::mma_sync(acc, afr[0][ks], b0, acc);
            wmma::mma_sync(acc, afr[0][ks], b1, acc);
            wmma::mma_sync(acc, afr[1][ks], b0, acc);
        }
        wmma::store_matrix_sync(&Sc[c * KCH + w * 16], acc, LSC, wmma::mem_row_major);
        __syncthreads();
        if (c + 2 < nchunk) loadK(c + 2, buf);
    }
    __syncthreads();

    // ---- per-warp exact top-u radix select + softmax + compact (4 rows/warp) ----
    int* H = hist + w * 256;
    for (int rr = 0; rr < 4; rr++) {
        const int r = w * 4 + rr;
        const float* row = &Sc[r * LSC];
        const long long grow = (long long)bh * SEQL + blockIdx.x * QROWS + r;
        unsigned prefix = 0;
        int kk = TOPU;
#pragma unroll
        for (int shift = 24; shift >= 0; shift -= 8) {
#pragma unroll
            for (int j = 0; j < 8; j++) H[lane * 8 + j] = 0;
            __syncwarp();
#pragma unroll
            for (int i = 0; i < 32; i++) {
                float v = row[lane + i * 32] * 0.125f;
                unsigned bits = __float_as_uint(v);
                unsigned key = (bits & 0x80000000u) ? ~bits : (bits | 0x80000000u);
                bool act = (shift == 24) || ((key >> (shift + 8)) == prefix);
                if (act) atomicAdd(&H[(key >> shift) & 255u], 1);
            }
            __syncwarp();
            int hloc[8], tot = 0;
#pragma unroll
            for (int j = 0; j < 8; j++) { hloc[j] = H[lane * 8 + j]; tot += hloc[j]; }
            int s = tot;
#pragma unroll
            for (int off = 1; off < 32; off <<= 1) {
                int t = __shfl_down_sync(0xffffffffu, s, off);
                if (lane + off < 32) s += t;
            }
            int run = s - tot;          // count of digits in lanes > lane
            int fdig = -1, fk = 0;
#pragma unroll
            for (int j = 7; j >= 0; j--) {
                run += hloc[j];
                if (fdig < 0 && run >= kk && run - hloc[j] < kk) { fdig = lane * 8 + j; fk = kk - (run - hloc[j]); }
            }
            unsigned ball = __ballot_sync(0xffffffffu, fdig >= 0);
            int src = __ffs(ball) - 1;
            prefix = (prefix << 8) | (unsigned)__shfl_sync(0xffffffffu, fdig, src);
            kk = __shfl_sync(0xffffffffu, fk, src);
            __syncwarp();
        }
        unsigned tbits = (prefix & 0x80000000u) ? (prefix ^ 0x80000000u) : ~prefix;
        float thr = __uint_as_float(tbits);

        float m = -3.0e38f;
#pragma unroll
        for (int i = 0; i < 32; i++) {
            float v = row[lane + i * 32] * 0.125f;
            if (v >= thr) m = fmaxf(m, v);
        }
#pragma unroll
        for (int off = 16; off > 0; off >>= 1) m = fmaxf(m, __shfl_xor_sync(0xffffffffu, m, off));
        float sum = 0.f;
#pragma unroll
        for (int i = 0; i < 32; i++) {
            float v = row[lane + i * 32] * 0.125f;
            if (v >= thr) sum += __expf(v - m);
        }
#pragma unroll
        for (int off = 16; off > 0; off >>= 1) sum += __shfl_xor_sync(0xffffffffu, sum, off);
        float inv = 1.f / sum;

        int basec = 0;
#pragma unroll
        for (int i = 0; i < 32; i++) {
            float v = row[lane + i * 32] * 0.125f;
            bool keep = (v >= thr);
            unsigned mk = __ballot_sync(0xffffffffu, keep);
            if (keep) {
                int pos = basec + __popc(mk & ((1u << lane) - 1u));
                if (pos < PSLOTS) {
                    pidx[grow * PSLOTS + pos] = lane + i * 32;
                    pval[grow * PSLOTS + pos] = __expf(v - m) * inv;
                }
            }
            basec += __popc(mk);
        }
        if (lane == 0) pcnt[grow] = min(basec, PSLOTS);
    }
}

// ---------------- one fused weight split ----------------
__global__ __launch_bounds__(256)
void wsplit_all(const float* __restrict__ We, const float* __restrict__ Wq,
                const float* __restrict__ Wk, const float* __restrict__ Wv,
                const float* __restrict__ Wo, const float* __restrict__ W1,
                const float* __restrict__ W2, const float* __restrict__ Wd,
                bf16* __restrict__ o0, bf16* __restrict__ o1)
{
    long long i4 = (long long)blockIdx.x * 256 + threadIdx.x;
    if (i4 >= WT_TOTAL / 4) return;
    long long i = i4 * 4;
    const float* src; long long off;
    if      (i < 65536)   { src = We; off = i; }
    else if (i < 851968)  { src = Wq; off = i - 65536; }
    else if (i < 1638400) { src = Wk; off = i - 851968; }
    else if (i < 2424832) { src = Wv; off = i - 1638400; }
    else if (i < 3211264) { src = Wo; off = i - 2424832; }
    else if (i < 6356992) { src = W1; off = i - 3211264; }
    else if (i < 9502720) { src = W2; off = i - 6356992; }
    else                  { src = Wd; off = i - 9502720; }
    float4 v = *(const float4*)(src + off);
    union { uint2 u; bf16 h[4]; } p0, p1;
    split2(v.x, p0.h[0], p1.h[0]);
    split2(v.y, p0.h[1], p1.h[1]);
    split2(v.z, p0.h[2], p1.h[2]);
    split2(v.w, p0.h[3], p1.h[3]);
    *(uint2*)&o0[i] = p0.u;
    *(uint2*)&o1[i] = p1.u;
}

__global__ void bcat_all(const float* __restrict__ bq, const float* __restrict__ bk,
                         float* __restrict__ o)
{
    int i = blockIdx.x * 256 + threadIdx.x;
    if (i >= NLAYERS * 2 * DMODEL) return;
    int l = i >> 10, j = i & 1023;
    o[i] = (j < DMODEL) ? bq[l * DMODEL + j] : bk[l * DMODEL + j - DMODEL];
}

__global__ __launch_bounds__(256)
void xsplit_t(const float* __restrict__ x, bf16* __restrict__ o0, bf16* __restrict__ o1)
{
    __shared__ float t[32][33];
    int m0 = blockIdx.x * 32, f0 = blockIdx.y * 32;
    int tx = threadIdx.x & 31, ty = threadIdx.x >> 5;
#pragma unroll
    for (int i = 0; i < 4; i++)
        t[ty + 8 * i][tx] = x[(long long)(m0 + ty + 8 * i) * INPUT_DIM + f0 + tx];
    __syncthreads();
#pragma unroll
    for (int i = 0; i < 4; i++) {
        float v = t[tx][ty + 8 * i];
        long long idx = (long long)(f0 + ty + 8 * i) * ROWS + m0 + tx;
        bf16 s0, s1; split2(v, s0, s1);
        o0[idx] = s0; o1[idx] = s1;
    }
}

__global__ __launch_bounds__(256)
void pe_t(float* __restrict__ h, const float* __restrict__ bemb,
          bf16* __restrict__ o0, bf16* __restrict__ o1)
{
    int f = blockIdx.x;
    const float cc = 0.01798894603901634f;
    const float scale = 22.62741699796952f;
    float div = __expf(-(float)(f & ~1) * cc);
    bool odd = f & 1;
    float bb = bemb[f];
    for (int m = threadIdx.x; m < ROWS; m += 256) {
        int pos = m & (SEQL - 1);
        float arg = (float)pos * div;
        float pe = odd ? cosf(arg) : sinf(arg);
        long long idx = (long long)f * ROWS + m;
        float v = (h[idx] + bb) * scale + pe;
        h[idx] = v;
        bf16 s0, s1; split2(v, s0, s1);
        o0[idx] = s0; o1[idx] = s1;
    }
}

// feature-major LN over features: block = 32 tokens; values cached in registers
__global__ __launch_bounds__(256)
void add_ln_t(const float* __restrict__ resid, const float* __restrict__ delta,
              const float* __restrict__ dbias, float* __restrict__ out,
              bf16* __restrict__ o0, bf16* __restrict__ o1,
              const float* __restrict__ g, const float* __restrict__ b)
{
    __shared__ float S[8][32], S2[8][32], Sm[32], Sr[32];
    int m = blockIdx.x * 32 + (threadIdx.x & 31);
    int w = threadIdx.x >> 5;
    float vloc[64];
    float s = 0.f, s2 = 0.f;
#pragma unroll
    for (int jj = 0; jj < 64; jj++) {
        int f = w * 64 + jj;
        float v = resid[(long long)f * ROWS + m] + delta[(long long)f * ROWS + m] + dbias[f];
        vloc[jj] = v;
        s += v; s2 += v * v;
    }
    S[w][threadIdx.x & 31] = s; S2[w][threadIdx.x & 31] = s2;
    __syncthreads();
    if (threadIdx.x < 32) {
        float a = 0.f, c = 0.f;
#pragma unroll
        for (int ww = 0; ww < 8; ww++) { a += S[ww][threadIdx.x]; c += S2[ww][threadIdx.x]; }
        float mean = a * (1.f / DMODEL);
        float var = c * (1.f / DMODEL) - mean * mean;
        Sm[threadIdx.x] = mean; Sr[threadIdx.x] = rsqrtf(var + 1e-5f);
    }
    __syncthreads();
    float mean = Sm[threadIdx.x & 31], rstd = Sr[threadIdx.x & 31];
#pragma unroll
    for (int jj = 0; jj < 64; jj++) {
        int f = w * 64 + jj;
        long long idx = (long long)f * ROWS + m;
        float o = (vloc[jj] - mean) * rstd * g[f] + b[f];
        out[idx] = o;
        bf16 s0, s1; split2(o, s0, s1);
        o0[idx] = s0; o1[idx] = s1;
    }
}

// ---------------- sparse PV gather ----------------
__global__ __launch_bounds__(256)
void pv_sparse(const int* __restrict__ pcnt, const int* __restrict__ pidx,
               const float* __restrict__ pval,
               const bf16* __restrict__ v0, const bf16* __restrict__ v1,
               bf16* __restrict__ a0, bf16* __restrict__ a1)
{
    int warpg = blockIdx.x * 8 + (threadIdx.x >> 5);
    int lane = threadIdx.x & 31;
    int bh = warpg >> 10, s = warpg & 1023;
    int b = bh >> 3, h = bh & 7;
    long long prow = (long long)warpg * PSLOTS;
    int cnt = pcnt[warpg];
    float accx = 0.f, accy = 0.f;

    for (int j0 = 0; j0 < cnt; j0 += 32) {
        int myj = j0 + lane;
        int t = 0; float p = 0.f;
        if (myj < cnt) { t = pidx[prow + myj]; p = pval[prow + myj]; }
        int lim = min(32, cnt - j0);
        for (int jj = 0; jj < lim; jj++) {
            int tt = __shfl_sync(0xffffffffu, t, jj);
            float pp = __shfl_sync(0xffffffffu, p, jj);
            long long vb = ((long long)(b * SEQL + tt)) * DMODEL + h * DK + lane * 2;
            uint32_t u0 = *(const uint32_t*)(v0 + vb);
            uint32_t u1 = *(const uint32_t*)(v1 + vb);
            __nv_bfloat162 h0 = *reinterpret_cast<__nv_bfloat162*>(&u0);
            __nv_bfloat162 h1 = *reinterpret_cast<__nv_bfloat162*>(&u1);
            float lo = __bfloat162float(h0.x) + __bfloat162float(h1.x);
            float hi = __bfloat162float(h0.y) + __bfloat162float(h1.y);
            accx = fmaf(pp, lo, accx);
            accy = fmaf(pp, hi, accy);
        }
    }
    long long ob = ((long long)(b * SEQL + s)) * DMODEL + h * DK + lane * 2;
    bf16 x0, x1, y0, y1;
    split2(accx, x0, x1);
    split2(accy, y0, y1);
    union { uint32_t u; bf16 hh[2]; } p0, p1;
    p0.hh[0] = x0; p0.hh[1] = y0;
    p1.hh[0] = x1; p1.hh[1] = y1;
    *(uint32_t*)(a0 + ob) = p0.u;
    *(uint32_t*)(a1 + ob) = p1.u;
}

// ---------------- host launch ----------------
extern "C" void kernel_launch(void* const* d_in, const int* in_sizes, int n_in,
                              void* d_out, int out_size)
{
    const float* x     = (const float*)d_in[0];
    const float* W_emb = (const float*)d_in[1];
    const float* b_emb = (const float*)d_in[2];
    const float* Wq    = (const float*)d_in[3];
    const float* bq    = (const float*)d_in[4];
    const float* Wk    = (const float*)d_in[5];
    const float* bk    = (const float*)d_in[6];
    const float* Wv    = (const float*)d_in[7];
    const float* bv    = (const float*)d_in[8];
    const float* Wo    = (const float*)d_in[9];
    const float* bo    = (const float*)d_in[10];
    const float* ln1_g = (const float*)d_in[11];
    const float* ln1_b = (const float*)d_in[12];
    const float* W1    = (const float*)d_in[13];
    const float* b1    = (const float*)d_in[14];
    const float* W2    = (const float*)d_in[15];
    const float* b2    = (const float*)d_in[16];
    const float* ln2_g = (const float*)d_in[17];
    const float* ln2_b = (const float*)d_in[18];
    const float* W_dec = (const float*)d_in[19];
    const float* b_dec = (const float*)d_in[20];
    float* out = (float*)d_out;

    float *h, *t2, *bcat, *pval;
    int *pidx, *pcnt;
    bf16 *x0, *x1, *h0, *h1, *qk0, *qk1, *v0, *v1, *a0, *a1, *f0, *f1, *w0, *w1;
    cudaGetSymbolAddress((void**)&h, g_h);
    cudaGetSymbolAddress((void**)&t2, g_t2);
    cudaGetSymbolAddress((void**)&bcat, g_bcat);
    cudaGetSymbolAddress((void**)&x0, g_x0);  cudaGetSymbolAddress((void**)&x1, g_x1);
    cudaGetSymbolAddress((void**)&h0, g_h0);  cudaGetSymbolAddress((void**)&h1, g_h1);
    cudaGetSymbolAddress((void**)&qk0, g_qk0); cudaGetSymbolAddress((void**)&qk1, g_qk1);
    cudaGetSymbolAddress((void**)&v0, g_v0);  cudaGetSymbolAddress((void**)&v1, g_v1);
    cudaGetSymbolAddress((void**)&a0, g_a0);  cudaGetSymbolAddress((void**)&a1, g_a1);
    cudaGetSymbolAddress((void**)&f0, g_f0);  cudaGetSymbolAddress((void**)&f1, g_f1);
    cudaGetSymbolAddress((void**)&pidx, g_pidx);
    cudaGetSymbolAddress((void**)&pval, g_pval);
    cudaGetSymbolAddress((void**)&pcnt, g_pcnt);
    cudaGetSymbolAddress((void**)&w0, g_w0);  cudaGetSymbolAddress((void**)&w1, g_w1);

    auto k128f = gk<128, 128, 0, 0, false, false>;  // emb / FF2
    auto kPRJ  = gk<128, 128, 0, 0, true,  false>;  // proj (B = token-major attn)
    auto kQK   = gk<128, 128, 1, 1, false, false>;
    auto kV    = gk<128, 128, 2, 1, false, false>;
    auto kFF1  = gk<128, 128, 1, 1, false, true>;
    auto kDec  = gk<128, 64, 2, 0, false, false>;
    const int SM128 = 104448;
    const int SMPRJ = 113664;
    const int SMDEC = 79872;
    const int SMSC  = QROWS * LSC * 4 + 2 * 2 * 64 * LKB * 2 + 2 * 64 * 16 * 2 + 4 * 256 * 4; // 115200
    cudaFuncSetAttribute(k128f, cudaFuncAttributeMaxDynamicSharedMemorySize, SM128);
    cudaFuncSetAttribute(kPRJ,  cudaFuncAttributeMaxDynamicSharedMemorySize, SMPRJ);
    cudaFuncSetAttribute(kQK,   cudaFuncAttributeMaxDynamicSharedMemorySize, SM128);
    cudaFuncSetAttribute(kV,    cudaFuncAttributeMaxDynamicSharedMemorySize, SM128);
    cudaFuncSetAttribute(kFF1,  cudaFuncAttributeMaxDynamicSharedMemorySize, SM128);
    cudaFuncSetAttribute(kDec,  cudaFuncAttributeMaxDynamicSharedMemorySize, SMDEC);
    cudaFuncSetAttribute(sc_topk, cudaFuncAttributeMaxDynamicSharedMemorySize, SMSC);

    wsplit_all<<<(int)((WT_TOTAL / 4 + 255) / 256), 256>>>(
        W_emb, Wq, Wk, Wv, Wo, W1, W2, W_dec, w0, w1);
    xsplit_t<<<dim3(ROWS / 32, INPUT_DIM / 32), 256>>>(x, x0, x1);
    k128f<<<dim3(32, 4, 1), 256, SM128>>>(
        w0 + W_EMB, w1 + W_EMB, DMODEL, 0, 0,
        x0, x1, ROWS, 0, 0,
        h, nullptr, nullptr, ROWS, 0, 0,
        INPUT_DIM, nullptr, 0, 1.f);
    pe_t<<<DMODEL, 256>>>(h, b_emb, h0, h1);
    bcat_all<<<(NLAYERS * 2 * DMODEL + 255) / 256, 256>>>(bq, bk, bcat);

    const long long QKOFF = (long long)DMODEL * ROWS;

    for (int l = 0; l < NLAYERS; l++) {
        // Q_t, K_t (fused; z=0 -> Q, z=1 -> K)
        kQK<<<dim3(32, 4, 2), 256, SM128>>>(
            w0 + W_Qo(l), w1 + W_Qo(l), DMODEL, 0, W_Ko(l) - W_Qo(l),
            h0, h1, ROWS, 0, 0,
            nullptr, qk0, qk1, ROWS, 0, QKOFF,
            DMODEL, bcat + l * 2 * DMODEL, DMODEL, 1.f);
        // V (token-major out)
        kV<<<dim3(4, 32, 1), 256, SM128>>>(
            h0, h1, ROWS, 0, 0,
            w0 + W_Vo(l), w1 + W_Vo(l), DMODEL, 0, 0,
            nullptr, v0, v1, DMODEL, 0, 0,
            DMODEL, bv + l * DMODEL, 0, 1.f);
        // fused scores + top-u + softmax -> compact sparse P (no DRAM scores)
        sc_topk<<<dim3(SEQL / QROWS, BH), 128, SMSC>>>(
            qk0, qk1, qk0 + QKOFF, qk1 + QKOFF, pcnt, pidx, pval);
        // sparse PV gather -> attn token-major
        pv_sparse<<<BH * SEQL / 8, 256>>>(pcnt, pidx, pval, v0, v1, a0, a1);
        // proj
        kPRJ<<<dim3(32, 4, 1), 256, SMPRJ>>>(
            w0 + W_Oo(l), w1 + W_Oo(l), DMODEL, 0, 0,
            a0, a1, DMODEL, 0, 0,
            t2, nullptr, nullptr, ROWS, 0, 0,
            DMODEL, nullptr, 0, 1.f);
        add_ln_t<<<ROWS / 32, 256>>>(h, t2, bo + l * DMODEL, h, h0, h1,
                                     ln1_g + l * DMODEL, ln1_b + l * DMODEL);
        // FF1
        kFF1<<<dim3(32, 16, 1), 256, SM128>>>(
            w0 + W_1o(l), w1 + W_1o(l), DFF, 0, 0,
            h0, h1, ROWS, 0, 0,
            nullptr, f0, f1, ROWS, 0, 0,
            DMODEL, b1 + l * DFF, 0, 1.f);
        // FF2
        k128f<<<dim3(32, 4, 1), 256, SM128>>>(
            w0 + W_2o(l), w1 + W_2o(l), DMODEL, 0, 0,
            f0, f1, ROWS, 0, 0,
            t2, nullptr, nullptr, ROWS, 0, 0,
            DFF, nullptr, 0, 1.f);
        add_ln_t<<<ROWS / 32, 256>>>(h, t2, b2 + l * DMODEL, h, h0, h1,
                                     ln2_g + l * DMODEL, ln2_b + l * DMODEL);
    }

    kDec<<<dim3(1, 32, 1), 256, SMDEC>>>(
        h0, h1, ROWS, 0, 0,
        w0 + W_DEC, w1 + W_DEC, NUM_CLASSES, 0, 0,
        out, nullptr, nullptr, NUM_CLASSES, 0, 0,
        DMODEL, b_dec, 0, 1.f);
}

// round 10
// speedup vs baseline: 1.2680x; 1.2680x over previous
#include <cuda_runtime.h>
#include <cuda_bf16.h>
#include <mma.h>
#include <cstdint>
#include <type_traits>
#include <math.h>
using namespace nvcuda;

#define BATCH 4
#define SEQL  1024
#define DMODEL 512
#define NHEAD 8
#define DK 64
#define NLAYERS 3
#define DFF 2048
#define INPUT_DIM 128
#define NUM_CLASSES 64
#define ROWS 4096
#define TOPU 34
#define BH 32
#define SB ((long long)SEQL*SEQL)
#define BK 32
#define NSTG 3
#define PSLOTS 128
typedef __nv_bfloat16 bf16;

// ---------------- scratch (static device globals) ----------------
__device__ __align__(16) float g_h [DMODEL*ROWS];
__device__ __align__(16) float g_t2[DMODEL*ROWS];
__device__ __align__(16) float g_sc[(long long)BH*SB];
__device__ __align__(16) float g_bcat[NLAYERS*2*DMODEL];
__device__ __align__(16) bf16 g_x0[INPUT_DIM*ROWS], g_x1[INPUT_DIM*ROWS];
__device__ __align__(16) bf16 g_h0[DMODEL*ROWS],  g_h1[DMODEL*ROWS];
__device__ __align__(16) bf16 g_qk0[2*DMODEL*ROWS], g_qk1[2*DMODEL*ROWS];
__device__ __align__(16) bf16 g_v0[ROWS*DMODEL],  g_v1[ROWS*DMODEL];
__device__ __align__(16) bf16 g_a0[ROWS*DMODEL],  g_a1[ROWS*DMODEL];
__device__ __align__(16) bf16 g_f0[DFF*ROWS],     g_f1[DFF*ROWS];
__device__ __align__(16) int   g_pidx[(long long)BH*SEQL*PSLOTS];
__device__ __align__(16) float g_pval[(long long)BH*SEQL*PSLOTS];
__device__ __align__(16) int   g_pcnt[BH*SEQL];

#define W_EMB 0
#define W_Qo(l) (65536LL   + (long long)(l)*262144)
#define W_Ko(l) (851968LL  + (long long)(l)*262144)
#define W_Vo(l) (1638400LL + (long long)(l)*262144)
#define W_Oo(l) (2424832LL + (long long)(l)*262144)
#define W_1o(l) (3211264LL + (long long)(l)*1048576)
#define W_2o(l) (6356992LL + (long long)(l)*1048576)
#define W_DEC 9502720LL
#define WT_TOTAL 9535488LL
__device__ __align__(16) bf16 g_w0[WT_TOTAL], g_w1[WT_TOTAL];

// ---------------- helpers ----------------
__device__ __forceinline__ uint32_t smem_to_u32(const void* p) {
    uint32_t a;
    asm("{ .reg .u64 t; cvta.to.shared.u64 t, %1; cvt.u32.u64 %0, t; }" : "=r"(a) : "l"(p));
    return a;
}
__device__ __forceinline__ void cp16(uint32_t s, const bf16* g) {
    asm volatile("{ .reg .u64 p; cvta.to.global.u64 p, %1; cp.async.cg.shared.global [%0], [p], 16; }"
                 :: "r"(s), "l"(g) : "memory");
}
__device__ __forceinline__ void cp_commit() { asm volatile("cp.async.commit_group;" ::: "memory"); }
__device__ __forceinline__ void cp_wait2()  { asm volatile("cp.async.wait_group 2;" ::: "memory"); }
__device__ __forceinline__ void cp_wait1()  { asm volatile("cp.async.wait_group 1;" ::: "memory"); }
__device__ __forceinline__ void cp_wait0()  { asm volatile("cp.async.wait_group 0;" ::: "memory"); }

__device__ __forceinline__ void split2(float v, bf16& s0, bf16& s1) {
    s0 = __float2bfloat16_rn(v);
    s1 = __float2bfloat16_rn(v - __bfloat162float(s0));
}

// ---------------- bf16x2 tensor GEMM (3-stage cp.async pipeline) ----------------
template<int MT, int NT, int BIAS, int EPI, bool BCOL, bool RELU>
__global__ __launch_bounds__(256, 2)
void gk(const bf16* __restrict__ A0, const bf16* __restrict__ A1,
        int lda, long long sAo, long long sAi,
        const bf16* __restrict__ B0, const bf16* __restrict__ B1,
        int ldb, long long sBo, long long sBi,
        float* __restrict__ C, bf16* __restrict__ C0, bf16* __restrict__ C1,
        int ldc, long long sCo, long long sCi,
        int K, const float* __restrict__ bias, long long sBias, float alpha)
{
    extern __shared__ char smc[];
    constexpr int LA = MT + 8;
    constexpr int SZA = BK * LA;
    constexpr int LB = BCOL ? (BK + 8) : (NT + 8);
    constexpr int SZB = BCOL ? (NT * LB) : (BK * LB);
    constexpr int A_ELEMS = NSTG * 2 * SZA;
    constexpr int LS = NT + 4;
    bf16* As = (bf16*)smc;
    bf16* Bs = As + A_ELEMS;
    float* stg = (float*)smc;

    const uint32_t smb = smem_to_u32(smc);
    const uint32_t smB = smb + A_ELEMS * 2;
    const int tid = threadIdx.x, wid = tid >> 5;
    const int z = blockIdx.z;
    const int bm = blockIdx.y * MT, bn = blockIdx.x * NT;
    const long long zA = (long long)(z >> 3) * sAo + (long long)(z & 7) * sAi;
    const long long zB = (long long)(z >> 3) * sBo + (long long)(z & 7) * sBi;
    const long long zC = (long long)(z >> 3) * sCo + (long long)(z & 7) * sCi;
    const bf16* Ap[2] = { A0 + zA, A1 + zA };
    const bf16* Bp[2] = { B0 + zB, B1 + zB };

    constexpr int WN_CNT = NT / 32;
    constexpr int WM = MT * WN_CNT / 8;
    constexpr int FM = WM / 16;
    const int wm = (wid / WN_CNT) * WM;
    const int wn = (wid % WN_CNT) * 32;

    using FragA = wmma::fragment<wmma::matrix_a, 16, 16, 16, bf16, wmma::col_major>;
    using BLay  = typename std::conditional<BCOL, wmma::col_major, wmma::row_major>::type;
    using FragB = wmma::fragment<wmma::matrix_b, 16, 16, 16, bf16, BLay>;
    wmma::fragment<wmma::accumulator, 16, 16, 16, float> acc[FM][2];
#pragma unroll
    for (int i = 0; i < FM; i++)
#pragma unroll
        for (int j = 0; j < 2; j++) wmma::fill_fragment(acc[i][j], 0.f);

    auto load_stage = [&](int c, int st) {
        const int k0 = c * BK;
#pragma unroll
        for (int p = 0; p < 2; p++) {
            const bf16* ap = Ap[p];
            for (int t = tid; t < 4 * MT; t += 256) {
                int k = t / (MT / 8), ch = t % (MT / 8);
                uint32_t d = smb + (uint32_t)(((st * 2 + p) * SZA + k * LA + ch * 8) * 2);
                cp16(d, ap + (long long)(k0 + k) * lda + bm + ch * 8);
            }
            const bf16* bp = Bp[p];
            if (!BCOL) {
                for (int t = tid; t < 4 * NT; t += 256) {
                    int k = t / (NT / 8), ch = t % (NT / 8);
                    uint32_t d = smB + (uint32_t)(((st * 2 + p) * SZB + k * LB + ch * 8) * 2);
                    cp16(d, bp + (long long)(k0 + k) * ldb + bn + ch * 8);
                }
            } else {
                for (int t = tid; t < 4 * NT; t += 256) {
                    int n = t >> 2, ch = t & 3;
                    uint32_t d = smB + (uint32_t)(((st * 2 + p) * SZB + n * LB + ch * 8) * 2);
                    cp16(d, bp + (long long)(bn + n) * ldb + k0 + ch * 8);
                }
            }
        }
        cp_commit();
    };

    const int nch = K / BK;
    load_stage(0, 0);
    load_stage(1, 1);

    for (int c = 0; c < nch; c++) {
        const int st = c % NSTG;
        if (c + 2 < nch) { load_stage(c + 2, (c + 2) % NSTG); cp_wait2(); }
        else if (c + 1 < nch) cp_wait1();
        else cp_wait0();
        __syncthreads();
#pragma unroll
        for (int ks = 0; ks < 2; ks++) {
            FragB bfr[2][2];
#pragma unroll
            for (int p = 0; p < 2; p++)
#pragma unroll
                for (int j = 0; j < 2; j++) {
                    const bf16* ptr = Bs + (st * 2 + p) * SZB +
                        (BCOL ? ((wn + j * 16) * LB + ks * 16) : (ks * 16 * LB + wn + j * 16));
                    wmma::load_matrix_sync(bfr[p][j], ptr, LB);
                }
#pragma unroll
            for (int i = 0; i < FM; i++) {
                FragA a0, a1;
                wmma::load_matrix_sync(a0, As + (st * 2 + 0) * SZA + ks * 16 * LA + wm + i * 16, LA);
                wmma::load_matrix_sync(a1, As + (st * 2 + 1) * SZA + ks * 16 * LA + wm + i * 16, LA);
#pragma unroll
                for (int j = 0; j < 2; j++) {
                    wmma::mma_sync(acc[i][j], a0, bfr[0][j], acc[i][j]);
                    wmma::mma_sync(acc[i][j], a0, bfr[1][j], acc[i][j]);
                    wmma::mma_sync(acc[i][j], a1, bfr[0][j], acc[i][j]);
                }
            }
        }
        __syncthreads();
    }

#pragma unroll
    for (int i = 0; i < FM; i++)
#pragma unroll
        for (int j = 0; j < 2; j++)
            wmma::store_matrix_sync(&stg[(wm + i * 16) * LS + wn + j * 16], acc[i][j], LS, wmma::mem_row_major);
    __syncthreads();

    for (int t = tid; t < MT * NT / 4; t += 256) {
        int row = t / (NT / 4), c4 = (t % (NT / 4)) * 4;
        float4 v = *(float4*)&stg[row * LS + c4];
        v.x *= alpha; v.y *= alpha; v.z *= alpha; v.w *= alpha;
        if (BIAS == 1) {
            float bb = bias[(z & 7) * sBias + bm + row];
            v.x += bb; v.y += bb; v.z += bb; v.w += bb;
        } else if (BIAS == 2) {
            const float* bp = bias + (z & 7) * sBias + bn + c4;
            v.x += bp[0]; v.y += bp[1]; v.z += bp[2]; v.w += bp[3];
        }
        if (RELU) {
            v.x = fmaxf(v.x, 0.f); v.y = fmaxf(v.y, 0.f);
            v.z = fmaxf(v.z, 0.f); v.w = fmaxf(v.w, 0.f);
        }
        long long idx = zC + (long long)(bm + row) * ldc + bn + c4;
        if (EPI == 0) {
            *(float4*)&C[idx] = v;
        } else {
            union { uint2 u; bf16 h[4]; } p0, p1;
            split2(v.x, p0.h[0], p1.h[0]);
            split2(v.y, p0.h[1], p1.h[1]);
            split2(v.z, p0.h[2], p1.h[2]);
            split2(v.w, p0.h[3], p1.h[3]);
            *(uint2*)&C0[idx] = p0.u;
            *(uint2*)&C1[idx] = p1.u;
        }
    }
}

// ---------------- one fused weight split ----------------
__global__ __launch_bounds__(256)
void wsplit_all(const float* __restrict__ We, const float* __restrict__ Wq,
                const float* __restrict__ Wk, const float* __restrict__ Wv,
                const float* __restrict__ Wo, const float* __restrict__ W1,
                const float* __restrict__ W2, const float* __restrict__ Wd,
                bf16* __restrict__ o0, bf16* __restrict__ o1)
{
    long long i4 = (long long)blockIdx.x * 256 + threadIdx.x;
    if (i4 >= WT_TOTAL / 4) return;
    long long i = i4 * 4;
    const float* src; long long off;
    if      (i < 65536)   { src = We; off = i; }
    else if (i < 851968)  { src = Wq; off = i - 65536; }
    else if (i < 1638400) { src = Wk; off = i - 851968; }
    else if (i < 2424832) { src = Wv; off = i - 1638400; }
    else if (i < 3211264) { src = Wo; off = i - 2424832; }
    else if (i < 6356992) { src = W1; off = i - 3211264; }
    else if (i < 9502720) { src = W2; off = i - 6356992; }
    else                  { src = Wd; off = i - 9502720; }
    float4 v = *(const float4*)(src + off);
    union { uint2 u; bf16 h[4]; } p0, p1;
    split2(v.x, p0.h[0], p1.h[0]);
    split2(v.y, p0.h[1], p1.h[1]);
    split2(v.z, p0.h[2], p1.h[2]);
    split2(v.w, p0.h[3], p1.h[3]);
    *(uint2*)&o0[i] = p0.u;
    *(uint2*)&o1[i] = p1.u;
}

__global__ void bcat_all(const float* __restrict__ bq, const float* __restrict__ bk,
                         float* __restrict__ o)
{
    int i = blockIdx.x * 256 + threadIdx.x;
    if (i >= NLAYERS * 2 * DMODEL) return;
    int l = i >> 10, j = i & 1023;
    o[i] = (j < DMODEL) ? bq[l * DMODEL + j] : bk[l * DMODEL + j - DMODEL];
}

__global__ __launch_bounds__(256)
void xsplit_t(const float* __restrict__ x, bf16* __restrict__ o0, bf16* __restrict__ o1)
{
    __shared__ float t[32][33];
    int m0 = blockIdx.x * 32, f0 = blockIdx.y * 32;
    int tx = threadIdx.x & 31, ty = threadIdx.x >> 5;
#pragma unroll
    for (int i = 0; i < 4; i++)
        t[ty + 8 * i][tx] = x[(long long)(m0 + ty + 8 * i) * INPUT_DIM + f0 + tx];
    __syncthreads();
#pragma unroll
    for (int i = 0; i < 4; i++) {
        float v = t[tx][ty + 8 * i];
        long long idx = (long long)(f0 + ty + 8 * i) * ROWS + m0 + tx;
        bf16 s0, s1; split2(v, s0, s1);
        o0[idx] = s0; o1[idx] = s1;
    }
}

__global__ __launch_bounds__(256)
void pe_t(float* __restrict__ h, const float* __restrict__ bemb,
          bf16* __restrict__ o0, bf16* __restrict__ o1)
{
    int f = blockIdx.x;
    const float cc = 0.01798894603901634f;
    const float scale = 22.62741699796952f;
    float div = __expf(-(float)(f & ~1) * cc);
    bool odd = f & 1;
    float bb = bemb[f];
    for (int m = threadIdx.x; m < ROWS; m += 256) {
        int pos = m & (SEQL - 1);
        float arg = (float)pos * div;
        float pe = odd ? cosf(arg) : sinf(arg);
        long long idx = (long long)f * ROWS + m;
        float v = (h[idx] + bb) * scale + pe;
        h[idx] = v;
        bf16 s0, s1; split2(v, s0, s1);
        o0[idx] = s0; o1[idx] = s1;
    }
}

// feature-major LN; values cached in registers (no re-read)
__global__ __launch_bounds__(256)
void add_ln_t(const float* __restrict__ resid, const float* __restrict__ delta,
              const float* __restrict__ dbias, float* __restrict__ out,
              bf16* __restrict__ o0, bf16* __restrict__ o1,
              const float* __restrict__ g, const float* __restrict__ b)
{
    __shared__ float S[8][32], S2[8][32], Sm[32], Sr[32];
    int m = blockIdx.x * 32 + (threadIdx.x & 31);
    int w = threadIdx.x >> 5;
    float vloc[64];
    float s = 0.f, s2 = 0.f;
#pragma unroll
    for (int jj = 0; jj < 64; jj++) {
        int f = w * 64 + jj;
        float v = resid[(long long)f * ROWS + m] + delta[(long long)f * ROWS + m] + dbias[f];
        vloc[jj] = v;
        s += v; s2 += v * v;
    }
    S[w][threadIdx.x & 31] = s; S2[w][threadIdx.x & 31] = s2;
    __syncthreads();
    if (threadIdx.x < 32) {
        float a = 0.f, c = 0.f;
#pragma unroll
        for (int ww = 0; ww < 8; ww++) { a += S[ww][threadIdx.x]; c += S2[ww][threadIdx.x]; }
        float mean = a * (1.f / DMODEL);
        float var = c * (1.f / DMODEL) - mean * mean;
        Sm[threadIdx.x] = mean; Sr[threadIdx.x] = rsqrtf(var + 1e-5f);
    }
    __syncthreads();
    float mean = Sm[threadIdx.x & 31], rstd = Sr[threadIdx.x & 31];
#pragma unroll
    for (int jj = 0; jj < 64; jj++) {
        int f = w * 64 + jj;
        long long idx = (long long)f * ROWS + m;
        float o = (vloc[jj] - mean) * rstd * g[f] + b[f];
        out[idx] = o;
        bf16 s0, s1; split2(o, s0, s1);
        o0[idx] = s0; o1[idx] = s1;
    }
}

// ---------------- exact top-u radix select + masked softmax -> compact sparse P ----------------
__global__ __launch_bounds__(256)
void topk_compact(const float* __restrict__ scores,
                  int* __restrict__ pcnt, int* __restrict__ pidx, float* __restrict__ pval)
{
    __shared__ int hist[256];
    __shared__ int wtot[8], wsufex[8];
    __shared__ float wredA[8], wredB[8];
    __shared__ unsigned s_prefix;
    __shared__ int s_k, scnt;

    long long base = (long long)blockIdx.x * SEQL;
    long long prow = (long long)blockIdx.x * PSLOTS;
    int tid = threadIdx.x, lane = tid & 31, w = tid >> 5;
    float4 v4 = *(const float4*)&scores[base + tid * 4];
    float val[4] = { v4.x, v4.y, v4.z, v4.w };
    unsigned key[4];
#pragma unroll
    for (int i = 0; i < 4; i++) {
        unsigned bits = __float_as_uint(val[i]);
        key[i] = (bits & 0x80000000u) ? ~bits : (bits | 0x80000000u);
    }
    if (tid == 0) { s_prefix = 0u; s_k = TOPU; scnt = 0; }
    __syncthreads();

    for (int shift = 24; shift >= 0; shift -= 8) {
        hist[tid] = 0;
        __syncthreads();
        unsigned pref = s_prefix;
        int k_cur = s_k;
#pragma unroll
        for (int i = 0; i < 4; i++) {
            bool active = (shift == 24) || ((key[i] >> (shift + 8)) == pref);
            if (active) atomicAdd(&hist[(key[i] >> shift) & 255u], 1);
        }
        __syncthreads();
        int own = hist[tid];
        int ssum = own;
#pragma unroll
        for (int off = 1; off < 32; off <<= 1) {
            int o = __shfl_down_sync(0xffffffffu, ssum, off);
            if (lane + off < 32) ssum += o;
        }
        if (lane == 0) wtot[w] = ssum;
        __syncthreads();
        if (tid < 8) {
            int e = 0;
            for (int j = tid + 1; j < 8; j++) e += wtot[j];
            wsufex[tid] = e;
        }
        __syncthreads();
        int suf = ssum + wsufex[w];
        if (suf >= k_cur && suf - own < k_cur) {
            s_prefix = (pref << 8) | (unsigned)tid;
            s_k = k_cur - (suf - own);
        }
        __syncthreads();
    }
    unsigned tkey = s_prefix;
    unsigned tbits = (tkey & 0x80000000u) ? (tkey ^ 0x80000000u) : ~tkey;
    float thr = __uint_as_float(tbits);

    float m = -3.0e38f;
#pragma unroll
    for (int i = 0; i < 4; i++) if (val[i] >= thr) m = fmaxf(m, val[i]);
#pragma unroll
    for (int off = 16; off > 0; off >>= 1) m = fmaxf(m, __shfl_xor_sync(0xffffffffu, m, off));
    if (lane == 0) wredA[w] = m;
    __syncthreads();
    if (w == 0) {
        float t = (lane < 8) ? wredA[lane] : -3.0e38f;
#pragma unroll
        for (int off = 4; off > 0; off >>= 1) t = fmaxf(t, __shfl_xor_sync(0xffffffffu, t, off));
        if (lane == 0) wredA[0] = t;
    }
    __syncthreads();
    m = wredA[0];

    float e[4]; float sum = 0.f;
#pragma unroll
    for (int i = 0; i < 4; i++) {
        e[i] = (val[i] >= thr) ? __expf(val[i] - m) : 0.f;
        sum += e[i];
    }
#pragma unroll
    for (int off = 16; off > 0; off >>= 1) sum += __shfl_xor_sync(0xffffffffu, sum, off);
    if (lane == 0) wredB[w] = sum;
    __syncthreads();
    if (w == 0) {
        float t = (lane < 8) ? wredB[lane] : 0.f;
#pragma unroll
        for (int off = 4; off > 0; off >>= 1) t += __shfl_xor_sync(0xffffffffu, t, off);
        if (lane == 0) wredB[0] = t;
    }
    __syncthreads();
    float inv = 1.f / wredB[0];

#pragma unroll
    for (int i = 0; i < 4; i++) {
        if (val[i] >= thr) {
            int pos = atomicAdd(&scnt, 1);
            if (pos < PSLOTS) {
                pidx[prow + pos] = tid * 4 + i;
                pval[prow + pos] = e[i] * inv;
            }
        }
    }
    __syncthreads();
    if (tid == 0) pcnt[blockIdx.x] = min(scnt, PSLOTS);
}

// ---------------- sparse PV gather ----------------
__global__ __launch_bounds__(256)
void pv_sparse(const int* __restrict__ pcnt, const int* __restrict__ pidx,
               const float* __restrict__ pval,
               const bf16* __restrict__ v0, const bf16* __restrict__ v1,
               bf16* __restrict__ a0, bf16* __restrict__ a1)
{
    int warpg = blockIdx.x * 8 + (threadIdx.x >> 5);
    int lane = threadIdx.x & 31;
    int bh = warpg >> 10, s = warpg & 1023;
    int b = bh >> 3, h = bh & 7;
    long long prow = (long long)warpg * PSLOTS;
    int cnt = pcnt[warpg];
    float accx = 0.f, accy = 0.f;

    for (int j0 = 0; j0 < cnt; j0 += 32) {
        int myj = j0 + lane;
        int t = 0; float p = 0.f;
        if (myj < cnt) { t = pidx[prow + myj]; p = pval[prow + myj]; }
        int lim = min(32, cnt - j0);
        for (int jj = 0; jj < lim; jj++) {
            int tt = __shfl_sync(0xffffffffu, t, jj);
            float pp = __shfl_sync(0xffffffffu, p, jj);
            long long vb = ((long long)(b * SEQL + tt)) * DMODEL + h * DK + lane * 2;
            uint32_t u0 = *(const uint32_t*)(v0 + vb);
            uint32_t u1 = *(const uint32_t*)(v1 + vb);
            __nv_bfloat162 h0 = *reinterpret_cast<__nv_bfloat162*>(&u0);
            __nv_bfloat162 h1 = *reinterpret_cast<__nv_bfloat162*>(&u1);
            float lo = __bfloat162float(h0.x) + __bfloat162float(h1.x);
            float hi = __bfloat162float(h0.y) + __bfloat162float(h1.y);
            accx = fmaf(pp, lo, accx);
            accy = fmaf(pp, hi, accy);
        }
    }
    long long ob = ((long long)(b * SEQL + s)) * DMODEL + h * DK + lane * 2;
    bf16 x0, x1, y0, y1;
    split2(accx, x0, x1);
    split2(accy, y0, y1);
    union { uint32_t u; bf16 hh[2]; } p0, p1;
    p0.hh[0] = x0; p0.hh[1] = y0;
    p1.hh[0] = x1; p1.hh[1] = y1;
    *(uint32_t*)(a0 + ob) = p0.u;
    *(uint32_t*)(a1 + ob) = p1.u;
}

// ---------------- host launch ----------------
extern "C" void kernel_launch(void* const* d_in, const int* in_sizes, int n_in,
                              void* d_out, int out_size)
{
    const float* x     = (const float*)d_in[0];
    const float* W_emb = (const float*)d_in[1];
    const float* b_emb = (const float*)d_in[2];
    const float* Wq    = (const float*)d_in[3];
    const float* bq    = (const float*)d_in[4];
    const float* Wk    = (const float*)d_in[5];
    const float* bk    = (const float*)d_in[6];
    const float* Wv    = (const float*)d_in[7];
    const float* bv    = (const float*)d_in[8];
    const float* Wo    = (const float*)d_in[9];
    const float* bo    = (const float*)d_in[10];
    const float* ln1_g = (const float*)d_in[11];
    const float* ln1_b = (const float*)d_in[12];
    const float* W1    = (const float*)d_in[13];
    const float* b1    = (const float*)d_in[14];
    const float* W2    = (const float*)d_in[15];
    const float* b2    = (const float*)d_in[16];
    const float* ln2_g = (const float*)d_in[17];
    const float* ln2_b = (const float*)d_in[18];
    const float* W_dec = (const float*)d_in[19];
    const float* b_dec = (const float*)d_in[20];
    float* out = (float*)d_out;

    float *h, *t2, *sc, *bcat, *pval;
    int *pidx, *pcnt;
    bf16 *x0, *x1, *h0, *h1, *qk0, *qk1, *v0, *v1, *a0, *a1, *f0, *f1, *w0, *w1;
    cudaGetSymbolAddress((void**)&h, g_h);
    cudaGetSymbolAddress((void**)&t2, g_t2);
    cudaGetSymbolAddress((void**)&sc, g_sc);
    cudaGetSymbolAddress((void**)&bcat, g_bcat);
    cudaGetSymbolAddress((void**)&x0, g_x0);  cudaGetSymbolAddress((void**)&x1, g_x1);
    cudaGetSymbolAddress((void**)&h0, g_h0);  cudaGetSymbolAddress((void**)&h1, g_h1);
    cudaGetSymbolAddress((void**)&qk0, g_qk0); cudaGetSymbolAddress((void**)&qk1, g_qk1);
    cudaGetSymbolAddress((void**)&v0, g_v0);  cudaGetSymbolAddress((void**)&v1, g_v1);
    cudaGetSymbolAddress((void**)&a0, g_a0);  cudaGetSymbolAddress((void**)&a1, g_a1);
    cudaGetSymbolAddress((void**)&f0, g_f0);  cudaGetSymbolAddress((void**)&f1, g_f1);
    cudaGetSymbolAddress((void**)&pidx, g_pidx);
    cudaGetSymbolAddress((void**)&pval, g_pval);
    cudaGetSymbolAddress((void**)&pcnt, g_pcnt);
    cudaGetSymbolAddress((void**)&w0, g_w0);  cudaGetSymbolAddress((void**)&w1, g_w1);

    auto k128f = gk<128, 128, 0, 0, false, false>;  // emb / FF2 / scores
    auto kPRJ  = gk<128, 128, 0, 0, true,  false>;  // proj (B = token-major attn)
    auto kQK   = gk<128, 128, 1, 1, false, false>;
    auto kV    = gk<128, 128, 2, 1, false, false>;
    auto kFF1  = gk<128, 128, 1, 1, false, true>;
    auto kDec  = gk<64, 64, 2, 0, false, false>;
    const int SM128 = 104448;
    const int SMPRJ = 113664;
    const int SMDEC = 55296;    // A: 3*2*(32*72)*2 = 27648 + B: 27648
    cudaFuncSetAttribute(k128f, cudaFuncAttributeMaxDynamicSharedMemorySize, SM128);
    cudaFuncSetAttribute(kPRJ,  cudaFuncAttributeMaxDynamicSharedMemorySize, SMPRJ);
    cudaFuncSetAttribute(kQK,   cudaFuncAttributeMaxDynamicSharedMemorySize, SM128);
    cudaFuncSetAttribute(kV,    cudaFuncAttributeMaxDynamicSharedMemorySize, SM128);
    cudaFuncSetAttribute(kFF1,  cudaFuncAttributeMaxDynamicSharedMemorySize, SM128);
    cudaFuncSetAttribute(kDec,  cudaFuncAttributeMaxDynamicSharedMemorySize, SMDEC);

    wsplit_all<<<(int)((WT_TOTAL / 4 + 255) / 256), 256>>>(
        W_emb, Wq, Wk, Wv, Wo, W1, W2, W_dec, w0, w1);
    xsplit_t<<<dim3(ROWS / 32, INPUT_DIM / 32), 256>>>(x, x0, x1);
    k128f<<<dim3(32, 4, 1), 256, SM128>>>(
        w0 + W_EMB, w1 + W_EMB, DMODEL, 0, 0,
        x0, x1, ROWS, 0, 0,
        h, nullptr, nullptr, ROWS, 0, 0,
        INPUT_DIM, nullptr, 0, 1.f);
    pe_t<<<DMODEL, 256>>>(h, b_emb, h0, h1);
    bcat_all<<<(NLAYERS * 2 * DMODEL + 255) / 256, 256>>>(bq, bk, bcat);

    const long long QKOFF = (long long)DMODEL * ROWS;

    for (int l = 0; l < NLAYERS; l++) {
        kQK<<<dim3(32, 4, 2), 256, SM128>>>(
            w0 + W_Qo(l), w1 + W_Qo(l), DMODEL, 0, W_Ko(l) - W_Qo(l),
            h0, h1, ROWS, 0, 0,
            nullptr, qk0, qk1, ROWS, 0, QKOFF,
            DMODEL, bcat + l * 2 * DMODEL, DMODEL, 1.f);
        kV<<<dim3(4, 32, 1), 256, SM128>>>(
            h0, h1, ROWS, 0, 0,
            w0 + W_Vo(l), w1 + W_Vo(l), DMODEL, 0, 0,
            nullptr, v0, v1, DMODEL, 0, 0,
            DMODEL, bv + l * DMODEL, 0, 1.f);
        // scores = (Q^T K) / 8 per (b,h)
        k128f<<<dim3(8, 8, BH), 256, SM128>>>(
            qk0, qk1, ROWS, SEQL, (long long)DK * ROWS,
            qk0 + QKOFF, qk1 + QKOFF, ROWS, SEQL, (long long)DK * ROWS,
            sc, nullptr, nullptr, SEQL, 8 * SB, SB,
            DK, nullptr, 0, 0.125f);
        topk_compact<<<BH * SEQL, 256>>>(sc, pcnt, pidx, pval);
        pv_sparse<<<BH * SEQL / 8, 256>>>(pcnt, pidx, pval, v0, v1, a0, a1);
        kPRJ<<<dim3(32, 4, 1), 256, SMPRJ>>>(
            w0 + W_Oo(l), w1 + W_Oo(l), DMODEL, 0, 0,
            a0, a1, DMODEL, 0, 0,
            t2, nullptr, nullptr, ROWS, 0, 0,
            DMODEL, nullptr, 0, 1.f);
        add_ln_t<<<ROWS / 32, 256>>>(h, t2, bo + l * DMODEL, h, h0, h1,
                                     ln1_g + l * DMODEL, ln1_b + l * DMODEL);
        kFF1<<<dim3(32, 16, 1), 256, SM128>>>(
            w0 + W_1o(l), w1 + W_1o(l), DFF, 0, 0,
            h0, h1, ROWS, 0, 0,
            nullptr, f0, f1, ROWS, 0, 0,
            DMODEL, b1 + l * DFF, 0, 1.f);
        k128f<<<dim3(32, 4, 1), 256, SM128>>>(
            w0 + W_2o(l), w1 + W_2o(l), DMODEL, 0, 0,
            f0, f1, ROWS, 0, 0,
            t2, nullptr, nullptr, ROWS, 0, 0,
            DFF, nullptr, 0, 1.f);
        add_ln_t<<<ROWS / 32, 256>>>(h, t2, b2 + l * DMODEL, h, h0, h1,
                                     ln2_g + l * DMODEL, ln2_b + l * DMODEL);
    }

    kDec<<<dim3(1, 64, 1), 256, SMDEC>>>(
        h0, h1, ROWS, 0, 0,
        w0 + W_DEC, w1 + W_DEC, NUM_CLASSES, 0, 0,
        out, nullptr, nullptr, NUM_CLASSES, 0, 0,
        DMODEL, b_dec, 0, 1.f);
}